// round 10
// baseline (speedup 1.0000x reference)
#include <cuda_runtime.h>
#include <cuda_fp16.h>

#define NN 50000
#define HD 128
#define EE 640000
#define GG 128
#define SPLIT 25088                      // 196 * 128, row split point

typedef unsigned int u32;
typedef unsigned short u16;
typedef unsigned long long u64;

// Scratch buffers
__device__ float g_bufA[NN * HD];
__device__ float g_bufB[NN * HD];
__device__ float g_bufC[NN * HD];
// Pre-split W: [layer][hi/lo][16384 halves], swizzled smem image.
__device__ __align__(16) u16 g_wsp[4 * 2 * 16384];
// CSR-by-dst scratch
__device__ int g_rp[NN + 1];
__device__ int g_cur[NN];
__device__ int g_ssrc[EE];
__device__ int g_bsum[256];

#define SCAN_B 196

__device__ __forceinline__ u32 smem_u32(const void* p) {
    u32 a;
    asm("{ .reg .u64 t; cvta.to.shared.u64 t, %1; cvt.u32.u64 %0, t; }"
        : "=r"(a) : "l"(p));
    return a;
}
__device__ __forceinline__ void mma_f16(float* d, const u32* a, const u32* b) {
    asm("mma.sync.aligned.m16n8k16.row.col.f32.f16.f16.f32 "
        "{%0,%1,%2,%3}, {%4,%5,%6,%7}, {%8,%9}, {%0,%1,%2,%3};"
        : "+f"(d[0]), "+f"(d[1]), "+f"(d[2]), "+f"(d[3])
        : "r"(a[0]), "r"(a[1]), "r"(a[2]), "r"(a[3]), "r"(b[0]), "r"(b[1]));
}
__device__ __forceinline__ void ldsm4(u32* r, u32 addr) {
    asm volatile("ldmatrix.sync.aligned.m8n8.x4.shared.b16 {%0,%1,%2,%3}, [%4];"
                 : "=r"(r[0]), "=r"(r[1]), "=r"(r[2]), "=r"(r[3]) : "r"(addr));
}
__device__ __forceinline__ void cp16(u32 smem, const void* g) {
    asm volatile("cp.async.cg.shared.global [%0], [%1], 16;"
                 :: "r"(smem), "l"(g) : "memory");
}
__device__ __forceinline__ int swz_idx(int r, int kh) {
    return r * 32 + ((((kh >> 3) ^ ((r >> 1) & 3)) << 3) | (kh & 7));
}

// ---------------------------------------------------------------------------
// W prep: f16 hi/lo split, transposed [n][k], k-chunked, swizzled.
// ---------------------------------------------------------------------------
__global__ void prep_w(const float* __restrict__ W1, const float* __restrict__ W2,
                       const float* __restrict__ W3, const float* __restrict__ W4,
                       u16* __restrict__ out)
{
    int t = blockIdx.x * 256 + threadIdx.x;
    int layer = t >> 14, e = t & 16383;
    int k = e >> 7, n = e & 127;
    const float* W = layer == 0 ? W1 : layer == 1 ? W2 : layer == 2 ? W3 : W4;
    float v = W[k * HD + n];
    __half hi = __float2half_rn(v);
    __half lo = __float2half_rn(v - __half2float(hi));
    int ch = k >> 5, kh = k & 31;
    int idx = ch * 4096 + swz_idx(n, kh);
    int base = layer * 32768;
    out[base + idx]         = __half_as_ushort(hi);
    out[base + 16384 + idx] = __half_as_ushort(lo);
}

// ---------------------------------------------------------------------------
// CSR build
// ---------------------------------------------------------------------------
__global__ void csr_zero(int* __restrict__ cnt)
{
    int t = blockIdx.x * blockDim.x + threadIdx.x;
    if (t < NN) cnt[t] = 0;
}
__global__ void csr_hist(const int* __restrict__ ei, int* __restrict__ cnt)
{
    int e = blockIdx.x * blockDim.x + threadIdx.x;
    if (e < EE) atomicAdd(cnt + __ldg(ei + 2 * e + 1), 1);
}
__global__ void csr_scan1(const int* __restrict__ cnt, int* __restrict__ bsum)
{
    __shared__ int s[256];
    int t = threadIdx.x, i = blockIdx.x * 256 + t;
    s[t] = (i < NN) ? cnt[i] : 0;
    __syncthreads();
    for (int o = 128; o > 0; o >>= 1) {
        if (t < o) s[t] += s[t + o];
        __syncthreads();
    }
    if (t == 0) bsum[blockIdx.x] = s[0];
}
__global__ void csr_scan2(int* __restrict__ bsum, int* __restrict__ rp)
{
    if (threadIdx.x == 0) {
        int run = 0;
        for (int b = 0; b < SCAN_B; b++) {
            int v = bsum[b];
            bsum[b] = run;
            run += v;
        }
        rp[NN] = run;
    }
}
__global__ void csr_scan3(const int* __restrict__ cnt, const int* __restrict__ bsum,
                          int* __restrict__ rp, int* __restrict__ cur)
{
    __shared__ int s[256];
    int t = threadIdx.x, i = blockIdx.x * 256 + t;
    int c = (i < NN) ? cnt[i] : 0;
    s[t] = c;
    __syncthreads();
    for (int o = 1; o < 256; o <<= 1) {
        int v = (t >= o) ? s[t - o] : 0;
        __syncthreads();
        s[t] += v;
        __syncthreads();
    }
    if (i < NN) {
        int excl = bsum[blockIdx.x] + s[t] - c;
        rp[i] = excl;
        cur[i] = excl;
    }
}
__global__ void csr_place(const int* __restrict__ ei, int* __restrict__ cur,
                          int* __restrict__ ssrc)
{
    int e = blockIdx.x * blockDim.x + threadIdx.x;
    if (e >= EE) return;
    int src = __ldg(ei + 2 * e);
    int dst = __ldg(ei + 2 * e + 1);
    int pos = atomicAdd(cur + dst, 1);
    ssrc[pos] = src;
}

// ---------------------------------------------------------------------------
// Atomic-free aggregate over dst rows [n0, n1):
// out[d,:] = h[d,:] + sum_{e in row d} h[ssrc[e],:]
// One warp per dst; 4-wide edge unroll.
// ---------------------------------------------------------------------------
__global__ void __launch_bounds__(256) csr_agg(
    const float* __restrict__ h, const int* __restrict__ rp,
    const int* __restrict__ ssrc, float* __restrict__ out, int n0, int n1)
{
    int d = n0 + ((blockIdx.x * blockDim.x + threadIdx.x) >> 5);
    if (d >= n1) return;
    int lane = threadIdx.x & 31;
    float4 acc = __ldg((const float4*)(h + (size_t)d * HD) + lane);
    int e = __ldg(rp + d), e1 = __ldg(rp + d + 1);
    for (; e + 4 <= e1; e += 4) {
        int s0 = __ldg(ssrc + e + 0);
        int s1 = __ldg(ssrc + e + 1);
        int s2 = __ldg(ssrc + e + 2);
        int s3 = __ldg(ssrc + e + 3);
        float4 v0 = __ldg((const float4*)(h + (size_t)s0 * HD) + lane);
        float4 v1 = __ldg((const float4*)(h + (size_t)s1 * HD) + lane);
        float4 v2 = __ldg((const float4*)(h + (size_t)s2 * HD) + lane);
        float4 v3 = __ldg((const float4*)(h + (size_t)s3 * HD) + lane);
        acc.x += (v0.x + v1.x) + (v2.x + v3.x);
        acc.y += (v0.y + v1.y) + (v2.y + v3.y);
        acc.z += (v0.z + v1.z) + (v2.z + v3.z);
        acc.w += (v0.w + v1.w) + (v2.w + v3.w);
    }
    for (; e < e1; ++e) {
        int s = __ldg(ssrc + e);
        float4 v = __ldg((const float4*)(h + (size_t)s * HD) + lane);
        acc.x += v.x; acc.y += v.y; acc.z += v.z; acc.w += v.w;
    }
    *((float4*)(out + (size_t)d * HD) + lane) = acc;
}

// ---------------------------------------------------------------------------
// Smem layout (bytes). Full-K resident.
// ---------------------------------------------------------------------------
#define SM_BB  0
#define SM_SC  512
#define SM_OF  1024
#define SM_W   1536
#define SM_A   (SM_W + 65536)
#define SM_TOT (SM_A + 65536)            // 132608 B -> 1 CTA/SM, 16 warps

// ---------------------------------------------------------------------------
// Split-f16 GEMM (3xF16) over rows [rbase, rbase + 128*gridDim.x) clipped to M.
// ---------------------------------------------------------------------------
template <bool DO_BN>
__global__ void __launch_bounds__(512, 1) gemm_f16(
    const float* __restrict__ A, const u16* __restrict__ wsp,
    const float* __restrict__ bias, const float* __restrict__ gam,
    const float* __restrict__ bet, const float* __restrict__ mmean,
    const float* __restrict__ mvar, float* __restrict__ out, int rbase, int M)
{
    extern __shared__ char sm[];
    const u32 sb = smem_u32(sm);
    float* const bbp = (float*)(sm + SM_BB);
    float* const scp = (float*)(sm + SM_SC);
    float* const ofp = (float*)(sm + SM_OF);

    const int tid = threadIdx.x, wid = tid >> 5, lane = tid & 31;
    const int g = lane >> 2, q = lane & 3;
    const int wm = wid & 3, wn = wid >> 2;
    const int row0 = rbase + blockIdx.x * 128;

    if (tid < 128) {
        bbp[tid] = bias[tid];
        float s = 1.f, o = 0.f;
        if (DO_BN) {
            s = gam[tid] * rsqrtf(mvar[tid] + 1e-3f);
            o = bet[tid] - mmean[tid] * s;
        }
        scp[tid] = s;
        ofp[tid] = o;
    }

#pragma unroll
    for (int i = 0; i < 8; i++) {
        int idx = tid + i * 512;
        cp16(sb + SM_W + idx * 16, (const char*)wsp + idx * 16);
    }

    {
        const int j4 = lane * 4;
        const int ch = lane >> 3;
        const int kh = j4 & 31;
#pragma unroll
        for (int i = 0; i < 8; i++) {
            int r = wid * 8 + i;
            int grow = row0 + r;
            float4 v = make_float4(0.f, 0.f, 0.f, 0.f);
            if (grow < M)
                v = *(const float4*)(A + (size_t)grow * HD + j4);
            __half hx = __float2half_rn(v.x), hy = __float2half_rn(v.y),
                   hz = __float2half_rn(v.z), hw = __float2half_rn(v.w);
            union { u16 s[4]; u64 u; } hp, lp;
            hp.s[0] = __half_as_ushort(hx); hp.s[1] = __half_as_ushort(hy);
            hp.s[2] = __half_as_ushort(hz); hp.s[3] = __half_as_ushort(hw);
            lp.s[0] = __half_as_ushort(__float2half_rn(v.x - __half2float(hx)));
            lp.s[1] = __half_as_ushort(__float2half_rn(v.y - __half2float(hy)));
            lp.s[2] = __half_as_ushort(__float2half_rn(v.z - __half2float(hz)));
            lp.s[3] = __half_as_ushort(__float2half_rn(v.w - __half2float(hw)));
            int hidx = swz_idx(r, kh);
            *(u64*)(sm + SM_A + ch * 16384 + hidx * 2) = hp.u;
            *(u64*)(sm + SM_A + ch * 16384 + 8192 + hidx * 2) = lp.u;
        }
    }

    float d[2][4][4];
#pragma unroll
    for (int mt = 0; mt < 2; mt++)
#pragma unroll
        for (int nt = 0; nt < 4; nt++)
#pragma unroll
            for (int c = 0; c < 4; c++) d[mt][nt][c] = 0.f;

    asm volatile("cp.async.commit_group;" ::: "memory");
    asm volatile("cp.async.wait_group 0;" ::: "memory");
    __syncthreads();

#pragma unroll
    for (int ch = 0; ch < 4; ++ch) {
        const u32 abase = sb + SM_A + ch * 16384;
        const u32 wbase = sb + SM_W + ch * 8192;
#pragma unroll
        for (int s = 0; s < 2; ++s) {
            u32 fa_hi[2][4], fa_lo[2][4];
            const int ar = wm * 32 + (lane & 7) + ((lane & 8) ? 8 : 0);
            const int aj = s * 2 + ((lane & 16) ? 1 : 0);
#pragma unroll
            for (int mt = 0; mt < 2; mt++) {
                int r = ar + mt * 16;
                u32 off = (u32)(r * 64 + ((aj ^ ((r >> 1) & 3)) << 4));
                ldsm4(fa_hi[mt], abase + off);
                ldsm4(fa_lo[mt], abase + 8192 + off);
            }
            u32 fb_hi[4][2], fb_lo[4][2];
            const int brb = wn * 32 + ((lane & 16) ? 8 : 0) + (lane & 7);
            const int bj = s * 2 + ((lane & 8) ? 1 : 0);
#pragma unroll
            for (int t = 0; t < 2; t++) {
                int r = brb + t * 16;
                u32 off = (u32)(r * 64 + ((bj ^ ((r >> 1) & 3)) << 4));
                u32 tmp[4];
                ldsm4(tmp, wbase + off);
                fb_hi[2 * t][0] = tmp[0]; fb_hi[2 * t][1] = tmp[1];
                fb_hi[2 * t + 1][0] = tmp[2]; fb_hi[2 * t + 1][1] = tmp[3];
                ldsm4(tmp, wbase + 32768 + off);
                fb_lo[2 * t][0] = tmp[0]; fb_lo[2 * t][1] = tmp[1];
                fb_lo[2 * t + 1][0] = tmp[2]; fb_lo[2 * t + 1][1] = tmp[3];
            }
#pragma unroll
            for (int mt = 0; mt < 2; mt++)
#pragma unroll
                for (int nt = 0; nt < 4; nt++)
                    mma_f16(d[mt][nt], fa_hi[mt], fb_hi[nt]);
#pragma unroll
            for (int mt = 0; mt < 2; mt++)
#pragma unroll
                for (int nt = 0; nt < 4; nt++)
                    mma_f16(d[mt][nt], fa_hi[mt], fb_lo[nt]);
#pragma unroll
            for (int mt = 0; mt < 2; mt++)
#pragma unroll
                for (int nt = 0; nt < 4; nt++)
                    mma_f16(d[mt][nt], fa_lo[mt], fb_hi[nt]);
        }
    }

    const int q2 = q * 2;
#pragma unroll
    for (int mt = 0; mt < 2; mt++) {
        int r0 = row0 + wm * 32 + mt * 16 + g;
#pragma unroll
        for (int nt = 0; nt < 4; nt++) {
            int col = wn * 32 + nt * 8 + q2;
            float s0 = scp[col], s1 = scp[col + 1];
            float o0 = ofp[col], o1 = ofp[col + 1];
            float B0 = bbp[col], B1 = bbp[col + 1];
            float v0 = fmaxf(d[mt][nt][0] + B0, 0.f) * s0 + o0;
            float v1 = fmaxf(d[mt][nt][1] + B1, 0.f) * s1 + o1;
            float v2 = fmaxf(d[mt][nt][2] + B0, 0.f) * s0 + o0;
            float v3 = fmaxf(d[mt][nt][3] + B1, 0.f) * s1 + o1;
            if (r0 < M)
                *(float2*)(out + (size_t)r0 * HD + col) = make_float2(v0, v1);
            if (r0 + 8 < M)
                *(float2*)(out + (size_t)(r0 + 8) * HD + col) = make_float2(v2, v3);
        }
    }
}

// ---------------------------------------------------------------------------
// Final graph readout: sorted batch -> chunked register accumulation.
// ---------------------------------------------------------------------------
#define SEG_CH 64
__global__ void seg_sum(const float* __restrict__ h,
                        const int* __restrict__ batch,
                        float* __restrict__ out)
{
    int n0 = blockIdx.x * SEG_CH;
    if (n0 >= NN) return;
    int j = threadIdx.x;
    int nend = n0 + SEG_CH;
    if (nend > NN) nend = NN;
    float acc = 0.f;
    int cur = __ldg(batch + n0);
    for (int n = n0; n < nend; ++n) {
        int b = __ldg(batch + n);
        if (b != cur) {
            atomicAdd(out + (size_t)cur * HD + j, acc);
            acc = 0.f;
            cur = b;
        }
        acc += __ldg(h + (size_t)n * HD + j);
    }
    atomicAdd(out + (size_t)cur * HD + j, acc);
}

__global__ void zero_out(float* __restrict__ out, int n)
{
    int t = blockIdx.x * blockDim.x + threadIdx.x;
    if (t < n) out[t] = 0.f;
}

extern "C" void kernel_launch(void* const* d_in, const int* in_sizes, int n_in,
                              void* d_out, int out_size)
{
    const float* x   = (const float*)d_in[0];
    const int*   ei  = (const int*)d_in[1];
    const int*   bat = (const int*)d_in[2];
    const float* W1  = (const float*)d_in[3];
    const float* b1  = (const float*)d_in[4];
    const float* g1  = (const float*)d_in[5];
    const float* be1 = (const float*)d_in[6];
    const float* mm1 = (const float*)d_in[7];
    const float* mv1 = (const float*)d_in[8];
    const float* W2  = (const float*)d_in[9];
    const float* b2  = (const float*)d_in[10];
    const float* W3  = (const float*)d_in[11];
    const float* b3  = (const float*)d_in[12];
    const float* g2  = (const float*)d_in[13];
    const float* be2 = (const float*)d_in[14];
    const float* mm2 = (const float*)d_in[15];
    const float* mv2 = (const float*)d_in[16];
    const float* W4  = (const float*)d_in[17];
    const float* b4  = (const float*)d_in[18];
    float* out = (float*)d_out;

    float *bufA, *bufB, *bufC;
    u16* wsp;
    int *rp, *cur, *ssrc, *bsum;
    cudaGetSymbolAddress((void**)&bufA, g_bufA);
    cudaGetSymbolAddress((void**)&bufB, g_bufB);
    cudaGetSymbolAddress((void**)&bufC, g_bufC);
    cudaGetSymbolAddress((void**)&wsp, g_wsp);
    cudaGetSymbolAddress((void**)&rp, g_rp);
    cudaGetSymbolAddress((void**)&cur, g_cur);
    cudaGetSymbolAddress((void**)&ssrc, g_ssrc);
    cudaGetSymbolAddress((void**)&bsum, g_bsum);

    cudaFuncSetAttribute(gemm_f16<true>,
                         cudaFuncAttributeMaxDynamicSharedMemorySize, SM_TOT);
    cudaFuncSetAttribute(gemm_f16<false>,
                         cudaFuncAttributeMaxDynamicSharedMemorySize, SM_TOT);

    static cudaStream_t s2 = nullptr;
    static cudaEvent_t evFork, evJoin, evG2, evAgg1b, evG3, evAgg2b;
    if (s2 == nullptr) {
        cudaStreamCreateWithFlags(&s2, cudaStreamNonBlocking);
        cudaEventCreateWithFlags(&evFork, cudaEventDisableTiming);
        cudaEventCreateWithFlags(&evJoin, cudaEventDisableTiming);
        cudaEventCreateWithFlags(&evG2, cudaEventDisableTiming);
        cudaEventCreateWithFlags(&evAgg1b, cudaEventDisableTiming);
        cudaEventCreateWithFlags(&evG3, cudaEventDisableTiming);
        cudaEventCreateWithFlags(&evAgg2b, cudaEventDisableTiming);
    }

    const int gemm_blocks  = (NN + 127) / 128;             // 391 (full)
    const int gemm_blocksA = SPLIT / 128;                  // 196 (rows 0..SPLIT)
    const int gemm_blocksB = (NN - SPLIT + 127) / 128;     // 195
    const int edge_blocks  = (EE + 255) / 256;
    const int aggA_blocks  = (SPLIT * 32 + 255) / 256;
    const int aggB_blocks  = ((NN - SPLIT) * 32 + 255) / 256;
    const int seg_blocks   = (NN + SEG_CH - 1) / SEG_CH;

    // Main: W prep, then fork the CSR chain to s2.
    prep_w<<<256, 256>>>(W1, W2, W3, W4, wsp);
    cudaEventRecord(evFork, 0);
    cudaStreamWaitEvent(s2, evFork, 0);
    csr_zero<<<(NN + 255) / 256, 256, 0, s2>>>(cur);
    csr_hist<<<edge_blocks, 256, 0, s2>>>(ei, cur);
    csr_scan1<<<SCAN_B, 256, 0, s2>>>(cur, bsum);
    csr_scan2<<<1, 32, 0, s2>>>(bsum, rp);
    csr_scan3<<<SCAN_B, 256, 0, s2>>>(cur, bsum, rp, cur);
    csr_place<<<edge_blocks, 256, 0, s2>>>(ei, cur, ssrc);
    cudaEventRecord(evJoin, s2);
    zero_out<<<(GG * HD + 255) / 256, 256, 0, s2>>>(out, GG * HD);

    // Main: G1, G2 (overlap with CSR build).
    gemm_f16<true><<<gemm_blocks, 512, SM_TOT>>>(
        x, wsp + 0 * 32768, b1, g1, be1, mm1, mv1, bufA, 0, NN);
    gemm_f16<false><<<gemm_blocks, 512, SM_TOT>>>(
        bufA, wsp + 1 * 32768, b2, nullptr, nullptr, nullptr, nullptr,
        bufB, 0, NN);
    cudaEventRecord(evG2, 0);

    // s2: agg1b (rows SPLIT..NN) — after CSR (stream order) and G2 (event).
    cudaStreamWaitEvent(s2, evG2, 0);
    csr_agg<<<aggB_blocks, 256, 0, s2>>>(bufB, rp, ssrc, bufC, SPLIT, NN);
    cudaEventRecord(evAgg1b, s2);

    // Main: agg1a, then G3a overlapping agg1b; join for G3b.
    cudaStreamWaitEvent(0, evJoin, 0);
    csr_agg<<<aggA_blocks, 256>>>(bufB, rp, ssrc, bufC, 0, SPLIT);
    gemm_f16<true><<<gemm_blocksA, 512, SM_TOT>>>(
        bufC, wsp + 2 * 32768, b3, g2, be2, mm2, mv2, bufA, 0, NN);
    cudaStreamWaitEvent(0, evAgg1b, 0);
    gemm_f16<true><<<gemm_blocksB, 512, SM_TOT>>>(
        bufC, wsp + 2 * 32768, b3, g2, be2, mm2, mv2, bufA, SPLIT, NN);
    cudaEventRecord(evG3, 0);

    // s2: agg2b after full G3.
    cudaStreamWaitEvent(s2, evG3, 0);
    csr_agg<<<aggB_blocks, 256, 0, s2>>>(bufA, rp, ssrc, bufB, SPLIT, NN);
    cudaEventRecord(evAgg2b, s2);

    // Main: agg2a, G4a overlapping agg2b, join, G4b, readout.
    csr_agg<<<aggA_blocks, 256>>>(bufA, rp, ssrc, bufB, 0, SPLIT);
    gemm_f16<false><<<gemm_blocksA, 512, SM_TOT>>>(
        bufB, wsp + 3 * 32768, b4, nullptr, nullptr, nullptr, nullptr,
        bufA, 0, NN);
    cudaStreamWaitEvent(0, evAgg2b, 0);
    gemm_f16<false><<<gemm_blocksB, 512, SM_TOT>>>(
        bufB, wsp + 3 * 32768, b4, nullptr, nullptr, nullptr, nullptr,
        bufA, SPLIT, NN);
    seg_sum<<<seg_blocks, 128>>>(bufA, bat, out);
}